// round 3
// baseline (speedup 1.0000x reference)
#include <cuda_runtime.h>
#include <cstdint>
#include <math.h>

// Problem constants
#define HN    1024
#define EMBD  512
#define VOC   32000
#define BB    16
#define SEQ   128
#define MROWS (BB*SEQ)   // 2048
#define G4    (4*HN)     // 4096

// Scratch (device globals: allocation-free)
__device__ float    g_XG[MROWS * G4];   // [2048,4096] input-gate projections
__device__ float    g_HS[MROWS * HN];   // [2048,1024] hidden states per step
__device__ float    g_H[BB * HN];
__device__ float    g_C[BB * HN];
__device__ unsigned g_bar;

__device__ __forceinline__ unsigned f2tf(float x){
    unsigned u; asm("cvt.rna.tf32.f32 %0, %1;" : "=r"(u) : "f"(x)); return u;
}

#define MMA_TF32(d, a0,a1,a2,a3, b0,b1) \
  asm volatile("mma.sync.aligned.m16n8k8.row.col.f32.tf32.tf32.f32 " \
    "{%0,%1,%2,%3}, {%4,%5,%6,%7}, {%8,%9}, {%0,%1,%2,%3};\n" \
    : "+f"(d[0]), "+f"(d[1]), "+f"(d[2]), "+f"(d[3]) \
    : "r"(a0), "r"(a1), "r"(a2), "r"(a3), "r"(b0), "r"(b1))

#define CP16(dst,src) asm volatile("cp.async.cg.shared.global [%0], [%1], 16;\n" :: "r"(dst), "l"(src))
#define CP_COMMIT()   asm volatile("cp.async.commit_group;\n")
#define CP_WAIT(n)    asm volatile("cp.async.wait_group %0;\n" :: "n"(n))

// ============================================================================
// TF32 GEMM: C[M,N] = A[M,K] @ B[N,K]^T + bias0 (+ bias1)
// A rows optionally gathered through gidx (embedding lookup).
// BM=128, BN=128, BK=32, 256 threads, 2-stage cp.async pipeline.
// Requires M%128==0, N%128==0, K%32==0 (true for all uses here).
// ============================================================================
template<int GATHER>
__global__ void __launch_bounds__(256) gemm_tf32(
    const float* __restrict__ A, const int* __restrict__ gidx,
    const float* __restrict__ B, const float* __restrict__ bias0,
    const float* __restrict__ bias1, float* __restrict__ C,
    int M, int N, int K)
{
    constexpr int BM=128, BN=128, BK=32, LD=36;   // pad 36 -> conflict-free frags
    extern __shared__ float smem[];
    float* As = smem;                 // [2][128][36]
    float* Bs = smem + 2*BM*LD;       // [2][128][36]

    const int tid  = threadIdx.x;
    const int lane = tid & 31, w = tid >> 5;
    const int bn0  = blockIdx.x * BN;
    const int bm0  = blockIdx.y * BM;
    const int mb   = (w & 3) * 32;    // warp M offset
    const int nb   = (w >> 2) * 64;   // warp N offset
    const int g    = lane >> 2, t4 = lane & 3;

    // per-thread loader setup: 4 A-float4 + 4 B-float4 per stage
    const float* asrc[4]; unsigned adst[4];
    const float* bsrc[4]; unsigned bdst[4];
    unsigned As_b = (unsigned)__cvta_generic_to_shared(As);
    unsigned Bs_b = (unsigned)__cvta_generic_to_shared(Bs);
    #pragma unroll
    for (int j=0;j<4;j++){
        int idx = tid + 256*j;
        int r = idx >> 3, c4 = idx & 7;
        const float* base;
        if (GATHER) base = A + (size_t)gidx[bm0 + r] * K;
        else        base = A + (size_t)(bm0 + r) * K;
        asrc[j] = base + c4*4;
        adst[j] = As_b + (unsigned)((r*LD + c4*4) * 4);
        bsrc[j] = B + (size_t)(bn0 + r) * K + c4*4;
        bdst[j] = Bs_b + (unsigned)((r*LD + c4*4) * 4);
    }
    const unsigned stS = BM*LD*4;     // stage stride (bytes)

    float acc[2][8][4];
    #pragma unroll
    for (int i=0;i<2;i++)
        #pragma unroll
        for (int j=0;j<8;j++)
            #pragma unroll
            for (int k=0;k<4;k++) acc[i][j][k]=0.f;

    const int niter = K / BK;
    // prologue: stage tiles 0 and 1
    #pragma unroll
    for (int j=0;j<4;j++){ CP16(adst[j], asrc[j]); CP16(bdst[j], bsrc[j]); }
    CP_COMMIT();
    #pragma unroll
    for (int j=0;j<4;j++){ CP16(adst[j]+stS, asrc[j]+BK); CP16(bdst[j]+stS, bsrc[j]+BK); }
    CP_COMMIT();
    CP_WAIT(1);
    __syncthreads();

    for (int it=0; it<niter; it++){
        const int s = it & 1;
        const float* As_ = As + s*BM*LD;
        const float* Bs_ = Bs + s*BM*LD;
        #pragma unroll
        for (int kk=0; kk<4; kk++){
            const int k = kk*8;
            unsigned a[2][4], b[8][2];
            #pragma unroll
            for (int am=0; am<2; am++){
                const float* p = As_ + (mb + am*16 + g)*LD + k + t4;
                a[am][0] = f2tf(p[0]);
                a[am][1] = f2tf(p[8*LD]);
                a[am][2] = f2tf(p[4]);
                a[am][3] = f2tf(p[8*LD+4]);
            }
            #pragma unroll
            for (int bn=0; bn<8; bn++){
                const float* p = Bs_ + (nb + bn*8 + g)*LD + k + t4;
                b[bn][0] = f2tf(p[0]);
                b[bn][1] = f2tf(p[4]);
            }
            #pragma unroll
            for (int am=0; am<2; am++)
                #pragma unroll
                for (int bn=0; bn<8; bn++)
                    MMA_TF32(acc[am][bn], a[am][0],a[am][1],a[am][2],a[am][3],
                             b[bn][0], b[bn][1]);
        }
        __syncthreads();
        if (it + 2 < niter){
            const int k0 = (it+2)*BK;
            const unsigned so = (unsigned)s*stS;
            #pragma unroll
            for (int j=0;j<4;j++){ CP16(adst[j]+so, asrc[j]+k0); CP16(bdst[j]+so, bsrc[j]+k0); }
            CP_COMMIT();
            CP_WAIT(1);
        } else {
            CP_WAIT(0);
        }
        __syncthreads();
    }

    // epilogue: bias add + float2 stores
    #pragma unroll
    for (int am=0; am<2; am++){
        int row = bm0 + mb + am*16 + g;
        #pragma unroll
        for (int bn=0; bn<8; bn++){
            int col = bn0 + nb + bn*8 + 2*t4;
            float b0v = bias0 ? bias0[col]   : 0.f;
            float b1v = bias0 ? bias0[col+1] : 0.f;
            if (bias1){ b0v += bias1[col]; b1v += bias1[col+1]; }
            float2 v0 = make_float2(acc[am][bn][0] + b0v, acc[am][bn][1] + b1v);
            float2 v1 = make_float2(acc[am][bn][2] + b0v, acc[am][bn][3] + b1v);
            *(float2*)(C + (size_t)row*N + col)     = v0;
            *(float2*)(C + (size_t)(row+8)*N + col) = v1;
        }
    }
}

// ============================================================================
// Persistent LSTM recurrence: 128 CTAs (1 per SM, all resident), each CTA
// owns 8 hidden units. W_hh slice (32 gate rows x 1024) lives in smem as
// TF32 for the whole kernel. Per step: grid barrier -> load h -> 8 warps
// do m16n8k8 TF32 MMA (split-K x2) -> fused sigmoid/tanh cell update.
// ============================================================================
__global__ void __launch_bounds__(256) lstm_kernel(const float* __restrict__ W_hh)
{
    constexpr int LDW = HN + 4;              // 1028: bank-conflict-free pad
    extern __shared__ float smem[];
    float* Ws = smem;                        // [32][1028] tf32 bits
    float* Hs = Ws + 32*LDW;                 // [16][1028] tf32 bits
    float* Gs = Hs + 16*LDW;                 // [2][16][32] fp32 gate partials

    const int tid  = threadIdx.x, lane = tid & 31, w = tid >> 5;
    const int u0   = blockIdx.x * 8;         // this CTA's hidden units
    const int gate = w & 3, half = w >> 2;   // warp -> (gate, K-half)
    const int g    = lane >> 2, t4 = lane & 3;
    unsigned* WsU = (unsigned*)Ws;
    unsigned* HsU = (unsigned*)Hs;

    // Load W_hh slice once: rows {gate*1024 + u0 + j}, convert to tf32
    #pragma unroll 4
    for (int j=0;j<32;j++){
        int idx = tid + 256*j;
        int r = idx >> 8, c4 = idx & 255;            // r: 0..31, 256 f4/row
        int grow = (r>>3)*HN + u0 + (r&7);
        float4 v = *(const float4*)(W_hh + (size_t)grow*HN + c4*4);
        unsigned* d = WsU + r*LDW + c4*4;
        d[0]=f2tf(v.x); d[1]=f2tf(v.y); d[2]=f2tf(v.z); d[3]=f2tf(v.w);
    }

    const unsigned nct = gridDim.x;
    for (int t=0; t<SEQ; t++){
        // ---- grid barrier (monotonic counter; reset by memset each launch)
        __threadfence();
        __syncthreads();
        if (tid == 0){
            atomicAdd(&g_bar, 1u);
            unsigned target = nct * (unsigned)(t+1);
            while (*(volatile unsigned*)&g_bar < target) { __nanosleep(64); }
        }
        __syncthreads();
        __threadfence();

        // ---- load h(t-1) -> smem (tf32)
        #pragma unroll 4
        for (int j=0;j<16;j++){
            int idx = tid + 256*j;
            int r = idx >> 8, c4 = idx & 255;
            float4 v = *(const float4*)(g_H + r*HN + c4*4);
            unsigned* d = HsU + r*LDW + c4*4;
            d[0]=f2tf(v.x); d[1]=f2tf(v.y); d[2]=f2tf(v.z); d[3]=f2tf(v.w);
        }
        __syncthreads();

        // ---- gates partial: C[16 batches][8 rows] over this warp's K-half
        float acc[4] = {0.f,0.f,0.f,0.f};
        {
            const int ks = half * (HN/2);
            const unsigned* pa0 = HsU + g*LDW      + t4 + ks;
            const unsigned* pa1 = HsU + (g+8)*LDW  + t4 + ks;
            const unsigned* pb  = WsU + (gate*8 + g)*LDW + t4 + ks;
            #pragma unroll 8
            for (int k=0; k<HN/2; k+=8){
                unsigned a0 = pa0[k], a2 = pa0[k+4];
                unsigned a1 = pa1[k], a3 = pa1[k+4];
                unsigned b0 = pb[k],  b1 = pb[k+4];
                MMA_TF32(acc, a0,a1,a2,a3, b0,b1);
            }
        }
        float* Gw = Gs + half*(16*32);
        Gw[g*32     + gate*8 + 2*t4    ] = acc[0];
        Gw[g*32     + gate*8 + 2*t4 + 1] = acc[1];
        Gw[(g+8)*32 + gate*8 + 2*t4    ] = acc[2];
        Gw[(g+8)*32 + gate*8 + 2*t4 + 1] = acc[3];
        __syncthreads();

        // ---- fused cell update: 16 batches x 8 units = 128 threads
        if (tid < 128){
            int b = tid >> 3, uu = tid & 7;
            const float* G0 = Gs + b*32;
            const float* G1 = Gs + 16*32 + b*32;
            size_t xb = ((size_t)b*SEQ + t)*G4 + u0 + uu;
            float vi = G0[uu]      + G1[uu]      + g_XG[xb];
            float vf = G0[8+uu]    + G1[8+uu]    + g_XG[xb + HN];
            float vg = G0[16+uu]   + G1[16+uu]   + g_XG[xb + 2*HN];
            float vo = G0[24+uu]   + G1[24+uu]   + g_XG[xb + 3*HN];
            float iv = 1.f/(1.f + expf(-vi));
            float fv = 1.f/(1.f + expf(-vf));
            float gv = tanhf(vg);
            float ov = 1.f/(1.f + expf(-vo));
            int hi = b*HN + u0 + uu;
            float cv = fv * g_C[hi] + iv * gv;
            float hv = ov * tanhf(cv);
            g_C[hi] = cv;
            g_H[hi] = hv;
            g_HS[((size_t)b*SEQ + t)*HN + u0 + uu] = hv;
        }
        // next iteration's barrier orders these global writes vs. reads
    }
}

// ============================================================================
// Launch
// ============================================================================
extern "C" void kernel_launch(void* const* d_in, const int* in_sizes, int n_in,
                              void* d_out, int out_size)
{
    const int*   tgt  = (const int*)  d_in[0];
    const float* h    = (const float*)d_in[1];
    const float* c    = (const float*)d_in[2];
    const float* emb  = (const float*)d_in[3];
    const float* W_ih = (const float*)d_in[4];
    const float* W_hh = (const float*)d_in[5];
    const float* b_ih = (const float*)d_in[6];
    const float* b_hh = (const float*)d_in[7];
    const float* W_fc = (const float*)d_in[8];
    const float* b_fc = (const float*)d_in[9];
    float* out = (float*)d_out;
    (void)in_sizes; (void)n_in; (void)out_size;

    void *pH, *pC, *pbar, *pXG, *pHS;
    cudaGetSymbolAddress(&pH,  g_H);
    cudaGetSymbolAddress(&pC,  g_C);
    cudaGetSymbolAddress(&pbar, g_bar);
    cudaGetSymbolAddress(&pXG, g_XG);
    cudaGetSymbolAddress(&pHS, g_HS);

    cudaMemcpyAsync(pH, h, BB*HN*sizeof(float), cudaMemcpyDeviceToDevice);
    cudaMemcpyAsync(pC, c, BB*HN*sizeof(float), cudaMemcpyDeviceToDevice);
    cudaMemsetAsync(pbar, 0, sizeof(unsigned));

    const int smem_g = 2*128*36*4 * 2;                    // 73,728 B
    const int smem_r = (32*1028 + 16*1028 + 2*16*32)*4;   // 201,472 B
    cudaFuncSetAttribute(gemm_tf32<1>, cudaFuncAttributeMaxDynamicSharedMemorySize, smem_g);
    cudaFuncSetAttribute(gemm_tf32<0>, cudaFuncAttributeMaxDynamicSharedMemorySize, smem_g);
    cudaFuncSetAttribute(lstm_kernel,  cudaFuncAttributeMaxDynamicSharedMemorySize, smem_r);

    // 1) XG = emb[tgt] @ W_ih^T + b_ih + b_hh   (M=2048,N=4096,K=512)
    dim3 g1(G4/128, MROWS/128);
    gemm_tf32<1><<<g1, 256, smem_g>>>(emb, tgt, W_ih, b_ih, b_hh,
                                      (float*)pXG, MROWS, G4, EMBD);

    // 2) 128-step recurrence, persistent (128 CTAs, all co-resident)
    lstm_kernel<<<128, 256, smem_r>>>(W_hh);

    // 3) logits = HS @ W_fc^T + b_fc            (M=2048,N=32000,K=1024)
    dim3 g2(VOC/128, MROWS/128);
    gemm_tf32<0><<<g2, 256, smem_g>>>((const float*)pHS, nullptr, W_fc, b_fc,
                                      nullptr, out, MROWS, VOC, HN);
}

// round 4
// speedup vs baseline: 1.0032x; 1.0032x over previous
#include <cuda_runtime.h>
#include <cstdint>
#include <math.h>

// Problem constants
#define HN    1024
#define EMBD  512
#define VOC   32000
#define BB    16
#define SEQ   128
#define MROWS (BB*SEQ)   // 2048
#define G4    (4*HN)     // 4096

// Scratch (device globals: allocation-free)
__device__ float    g_XG[MROWS * G4];   // [2048,4096] input-gate projections
__device__ float    g_HS[MROWS * HN];   // [2048,1024] hidden states per step
__device__ float    g_H[BB * HN];
__device__ float    g_C[BB * HN];
__device__ unsigned g_bar;

__device__ __forceinline__ unsigned f2tf(float x){
    unsigned u; asm("cvt.rna.tf32.f32 %0, %1;" : "=r"(u) : "f"(x)); return u;
}

#define MMA_TF32(d, a0,a1,a2,a3, b0,b1) \
  asm volatile("mma.sync.aligned.m16n8k8.row.col.f32.tf32.tf32.f32 " \
    "{%0,%1,%2,%3}, {%4,%5,%6,%7}, {%8,%9}, {%0,%1,%2,%3};\n" \
    : "+f"(d[0]), "+f"(d[1]), "+f"(d[2]), "+f"(d[3]) \
    : "r"(a0), "r"(a1), "r"(a2), "r"(a3), "r"(b0), "r"(b1))

#define CP16(dst,src) asm volatile("cp.async.cg.shared.global [%0], [%1], 16;\n" :: "r"(dst), "l"(src))
#define CP_COMMIT()   asm volatile("cp.async.commit_group;\n")
#define CP_WAIT(n)    asm volatile("cp.async.wait_group %0;\n" :: "n"(n))

// ============================================================================
// TF32 GEMM: C[M,N] = A[M,K] @ B[N,K]^T + bias0 (+ bias1)
// A rows optionally gathered through gidx (embedding lookup).
// BM=128, BN=128, BK=32, 256 threads, 2-stage cp.async pipeline.
// Requires M%128==0, N%128==0, K%32==0 (true for all uses here).
// ============================================================================
template<int GATHER>
__global__ void __launch_bounds__(256) gemm_tf32(
    const float* __restrict__ A, const int* __restrict__ gidx,
    const float* __restrict__ B, const float* __restrict__ bias0,
    const float* __restrict__ bias1, float* __restrict__ C,
    int M, int N, int K)
{
    constexpr int BM=128, BN=128, BK=32, LD=36;   // pad 36 -> conflict-free frags
    extern __shared__ float smem[];
    float* As = smem;                 // [2][128][36]
    float* Bs = smem + 2*BM*LD;       // [2][128][36]

    const int tid  = threadIdx.x;
    const int lane = tid & 31, w = tid >> 5;
    const int bn0  = blockIdx.x * BN;
    const int bm0  = blockIdx.y * BM;
    const int mb   = (w & 3) * 32;    // warp M offset
    const int nb   = (w >> 2) * 64;   // warp N offset
    const int g    = lane >> 2, t4 = lane & 3;

    // per-thread loader setup: 4 A-float4 + 4 B-float4 per stage
    const float* asrc[4]; unsigned adst[4];
    const float* bsrc[4]; unsigned bdst[4];
    unsigned As_b = (unsigned)__cvta_generic_to_shared(As);
    unsigned Bs_b = (unsigned)__cvta_generic_to_shared(Bs);
    #pragma unroll
    for (int j=0;j<4;j++){
        int idx = tid + 256*j;
        int r = idx >> 3, c4 = idx & 7;
        const float* base;
        if (GATHER) base = A + (size_t)gidx[bm0 + r] * K;
        else        base = A + (size_t)(bm0 + r) * K;
        asrc[j] = base + c4*4;
        adst[j] = As_b + (unsigned)((r*LD + c4*4) * 4);
        bsrc[j] = B + (size_t)(bn0 + r) * K + c4*4;
        bdst[j] = Bs_b + (unsigned)((r*LD + c4*4) * 4);
    }
    const unsigned stS = BM*LD*4;     // stage stride (bytes)

    float acc[2][8][4];
    #pragma unroll
    for (int i=0;i<2;i++)
        #pragma unroll
        for (int j=0;j<8;j++)
            #pragma unroll
            for (int k=0;k<4;k++) acc[i][j][k]=0.f;

    const int niter = K / BK;
    // prologue: stage tiles 0 and 1
    #pragma unroll
    for (int j=0;j<4;j++){ CP16(adst[j], asrc[j]); CP16(bdst[j], bsrc[j]); }
    CP_COMMIT();
    #pragma unroll
    for (int j=0;j<4;j++){ CP16(adst[j]+stS, asrc[j]+BK); CP16(bdst[j]+stS, bsrc[j]+BK); }
    CP_COMMIT();
    CP_WAIT(1);
    __syncthreads();

    for (int it=0; it<niter; it++){
        const int s = it & 1;
        const float* As_ = As + s*BM*LD;
        const float* Bs_ = Bs + s*BM*LD;
        #pragma unroll
        for (int kk=0; kk<4; kk++){
            const int k = kk*8;
            unsigned a[2][4], b[8][2];
            #pragma unroll
            for (int am=0; am<2; am++){
                const float* p = As_ + (mb + am*16 + g)*LD + k + t4;
                a[am][0] = f2tf(p[0]);
                a[am][1] = f2tf(p[8*LD]);
                a[am][2] = f2tf(p[4]);
                a[am][3] = f2tf(p[8*LD+4]);
            }
            #pragma unroll
            for (int bn=0; bn<8; bn++){
                const float* p = Bs_ + (nb + bn*8 + g)*LD + k + t4;
                b[bn][0] = f2tf(p[0]);
                b[bn][1] = f2tf(p[4]);
            }
            #pragma unroll
            for (int am=0; am<2; am++)
                #pragma unroll
                for (int bn=0; bn<8; bn++)
                    MMA_TF32(acc[am][bn], a[am][0],a[am][1],a[am][2],a[am][3],
                             b[bn][0], b[bn][1]);
        }
        __syncthreads();
        if (it + 2 < niter){
            const int k0 = (it+2)*BK;
            const unsigned so = (unsigned)s*stS;
            #pragma unroll
            for (int j=0;j<4;j++){ CP16(adst[j]+so, asrc[j]+k0); CP16(bdst[j]+so, bsrc[j]+k0); }
            CP_COMMIT();
            CP_WAIT(1);
        } else {
            CP_WAIT(0);
        }
        __syncthreads();
    }

    // epilogue: bias add + float2 stores
    #pragma unroll
    for (int am=0; am<2; am++){
        int row = bm0 + mb + am*16 + g;
        #pragma unroll
        for (int bn=0; bn<8; bn++){
            int col = bn0 + nb + bn*8 + 2*t4;
            float b0v = bias0 ? bias0[col]   : 0.f;
            float b1v = bias0 ? bias0[col+1] : 0.f;
            if (bias1){ b0v += bias1[col]; b1v += bias1[col+1]; }
            float2 v0 = make_float2(acc[am][bn][0] + b0v, acc[am][bn][1] + b1v);
            float2 v1 = make_float2(acc[am][bn][2] + b0v, acc[am][bn][3] + b1v);
            *(float2*)(C + (size_t)row*N + col)     = v0;
            *(float2*)(C + (size_t)(row+8)*N + col) = v1;
        }
    }
}

// ============================================================================
// Persistent LSTM recurrence: 128 CTAs (1 per SM, all resident), each CTA
// owns 8 hidden units. W_hh slice (32 gate rows x 1024) lives in smem as
// TF32 for the whole kernel. Per step: grid barrier -> load h -> 8 warps
// do m16n8k8 TF32 MMA (split-K x2) -> fused sigmoid/tanh cell update.
// ============================================================================
__global__ void __launch_bounds__(256) lstm_kernel(const float* __restrict__ W_hh)
{
    constexpr int LDW = HN + 4;              // 1028: bank-conflict-free pad
    extern __shared__ float smem[];
    float* Ws = smem;                        // [32][1028] tf32 bits
    float* Hs = Ws + 32*LDW;                 // [16][1028] tf32 bits
    float* Gs = Hs + 16*LDW;                 // [2][16][32] fp32 gate partials

    const int tid  = threadIdx.x, lane = tid & 31, w = tid >> 5;
    const int u0   = blockIdx.x * 8;         // this CTA's hidden units
    const int gate = w & 3, half = w >> 2;   // warp -> (gate, K-half)
    const int g    = lane >> 2, t4 = lane & 3;
    unsigned* WsU = (unsigned*)Ws;
    unsigned* HsU = (unsigned*)Hs;

    // Load W_hh slice once: rows {gate*1024 + u0 + j}, convert to tf32
    #pragma unroll 4
    for (int j=0;j<32;j++){
        int idx = tid + 256*j;
        int r = idx >> 8, c4 = idx & 255;            // r: 0..31, 256 f4/row
        int grow = (r>>3)*HN + u0 + (r&7);
        float4 v = *(const float4*)(W_hh + (size_t)grow*HN + c4*4);
        unsigned* d = WsU + r*LDW + c4*4;
        d[0]=f2tf(v.x); d[1]=f2tf(v.y); d[2]=f2tf(v.z); d[3]=f2tf(v.w);
    }

    const unsigned nct = gridDim.x;
    for (int t=0; t<SEQ; t++){
        // ---- grid barrier (monotonic counter; reset by memset each launch)
        __threadfence();
        __syncthreads();
        if (tid == 0){
            atomicAdd(&g_bar, 1u);
            unsigned target = nct * (unsigned)(t+1);
            while (*(volatile unsigned*)&g_bar < target) { __nanosleep(64); }
        }
        __syncthreads();
        __threadfence();

        // ---- load h(t-1) -> smem (tf32)
        #pragma unroll 4
        for (int j=0;j<16;j++){
            int idx = tid + 256*j;
            int r = idx >> 8, c4 = idx & 255;
            float4 v = *(const float4*)(g_H + r*HN + c4*4);
            unsigned* d = HsU + r*LDW + c4*4;
            d[0]=f2tf(v.x); d[1]=f2tf(v.y); d[2]=f2tf(v.z); d[3]=f2tf(v.w);
        }
        __syncthreads();

        // ---- gates partial: C[16 batches][8 rows] over this warp's K-half
        float acc[4] = {0.f,0.f,0.f,0.f};
        {
            const int ks = half * (HN/2);
            const unsigned* pa0 = HsU + g*LDW      + t4 + ks;
            const unsigned* pa1 = HsU + (g+8)*LDW  + t4 + ks;
            const unsigned* pb  = WsU + (gate*8 + g)*LDW + t4 + ks;
            #pragma unroll 8
            for (int k=0; k<HN/2; k+=8){
                unsigned a0 = pa0[k], a2 = pa0[k+4];
                unsigned a1 = pa1[k], a3 = pa1[k+4];
                unsigned b0 = pb[k],  b1 = pb[k+4];
                MMA_TF32(acc, a0,a1,a2,a3, b0,b1);
            }
        }
        float* Gw = Gs + half*(16*32);
        Gw[g*32     + gate*8 + 2*t4    ] = acc[0];
        Gw[g*32     + gate*8 + 2*t4 + 1] = acc[1];
        Gw[(g+8)*32 + gate*8 + 2*t4    ] = acc[2];
        Gw[(g+8)*32 + gate*8 + 2*t4 + 1] = acc[3];
        __syncthreads();

        // ---- fused cell update: 16 batches x 8 units = 128 threads
        if (tid < 128){
            int b = tid >> 3, uu = tid & 7;
            const float* G0 = Gs + b*32;
            const float* G1 = Gs + 16*32 + b*32;
            size_t xb = ((size_t)b*SEQ + t)*G4 + u0 + uu;
            float vi = G0[uu]      + G1[uu]      + g_XG[xb];
            float vf = G0[8+uu]    + G1[8+uu]    + g_XG[xb + HN];
            float vg = G0[16+uu]   + G1[16+uu]   + g_XG[xb + 2*HN];
            float vo = G0[24+uu]   + G1[24+uu]   + g_XG[xb + 3*HN];
            float iv = 1.f/(1.f + expf(-vi));
            float fv = 1.f/(1.f + expf(-vf));
            float gv = tanhf(vg);
            float ov = 1.f/(1.f + expf(-vo));
            int hi = b*HN + u0 + uu;
            float cv = fv * g_C[hi] + iv * gv;
            float hv = ov * tanhf(cv);
            g_C[hi] = cv;
            g_H[hi] = hv;
            g_HS[((size_t)b*SEQ + t)*HN + u0 + uu] = hv;
        }
        // next iteration's barrier orders these global writes vs. reads
    }
}

// ============================================================================
// Launch
// ============================================================================
extern "C" void kernel_launch(void* const* d_in, const int* in_sizes, int n_in,
                              void* d_out, int out_size)
{
    const int*   tgt  = (const int*)  d_in[0];
    const float* h    = (const float*)d_in[1];
    const float* c    = (const float*)d_in[2];
    const float* emb  = (const float*)d_in[3];
    const float* W_ih = (const float*)d_in[4];
    const float* W_hh = (const float*)d_in[5];
    const float* b_ih = (const float*)d_in[6];
    const float* b_hh = (const float*)d_in[7];
    const float* W_fc = (const float*)d_in[8];
    const float* b_fc = (const float*)d_in[9];
    float* out = (float*)d_out;
    (void)in_sizes; (void)n_in; (void)out_size;

    void *pH, *pC, *pbar, *pXG, *pHS;
    cudaGetSymbolAddress(&pH,  g_H);
    cudaGetSymbolAddress(&pC,  g_C);
    cudaGetSymbolAddress(&pbar, g_bar);
    cudaGetSymbolAddress(&pXG, g_XG);
    cudaGetSymbolAddress(&pHS, g_HS);

    cudaMemcpyAsync(pH, h, BB*HN*sizeof(float), cudaMemcpyDeviceToDevice);
    cudaMemcpyAsync(pC, c, BB*HN*sizeof(float), cudaMemcpyDeviceToDevice);
    cudaMemsetAsync(pbar, 0, sizeof(unsigned));

    const int smem_g = 2*128*36*4 * 2;                    // 73,728 B
    const int smem_r = (32*1028 + 16*1028 + 2*16*32)*4;   // 201,472 B
    cudaFuncSetAttribute(gemm_tf32<1>, cudaFuncAttributeMaxDynamicSharedMemorySize, smem_g);
    cudaFuncSetAttribute(gemm_tf32<0>, cudaFuncAttributeMaxDynamicSharedMemorySize, smem_g);
    cudaFuncSetAttribute(lstm_kernel,  cudaFuncAttributeMaxDynamicSharedMemorySize, smem_r);

    // 1) XG = emb[tgt] @ W_ih^T + b_ih + b_hh   (M=2048,N=4096,K=512)
    dim3 g1(G4/128, MROWS/128);
    gemm_tf32<1><<<g1, 256, smem_g>>>(emb, tgt, W_ih, b_ih, b_hh,
                                      (float*)pXG, MROWS, G4, EMBD);

    // 2) 128-step recurrence, persistent (128 CTAs, all co-resident)
    lstm_kernel<<<128, 256, smem_r>>>(W_hh);

    // 3) logits = HS @ W_fc^T + b_fc            (M=2048,N=32000,K=1024)
    dim3 g2(VOC/128, MROWS/128);
    gemm_tf32<0><<<g2, 256, smem_g>>>((const float*)pHS, nullptr, W_fc, b_fc,
                                      nullptr, out, MROWS, VOC, HN);
}